// round 2
// baseline (speedup 1.0000x reference)
#include <cuda_runtime.h>
#include <cuda_bf16.h>

// DIST_loss: loss = sum_i ||preds_i - targets_i||_2 / (N+1)
// preds, targets: [N, 2] float32 (interleaved x,y). Output: 1 float.
//
// HBM-bound streaming reduction.
//   Stage 1: grid-stride, 4x-unrolled float4 loads (8 independent LDG.128 per
//            iter -> MLP>=8), 4 independent accumulators, warp+smem reduce,
//            one partial per block into __device__ scratch.
//   Stage 2: one block reduces the fixed partial array in double, scales by
//            1/(N+1).
// Deterministic (no float atomics), allocation-free, graph-capturable.

#define RED_BLOCKS 2048
#define RED_THREADS 256

__device__ float g_partials[RED_BLOCKS];

__device__ __forceinline__ float pair_dist2(float4 a, float4 b, float& s2)
{
    float dx0 = a.x - b.x;
    float dy0 = a.y - b.y;
    float dx1 = a.z - b.z;
    float dy1 = a.w - b.w;
    s2 = sqrtf(fmaf(dx1, dx1, dy1 * dy1));
    return sqrtf(fmaf(dx0, dx0, dy0 * dy0));
}

__global__ __launch_bounds__(RED_THREADS)
void dist_reduce_stage1(const float4* __restrict__ preds4,
                        const float4* __restrict__ targs4,
                        int n4, int n_points)
{
    const int tid = blockIdx.x * blockDim.x + threadIdx.x;
    const int stride = gridDim.x * blockDim.x;

    float s0 = 0.0f, s1 = 0.0f, s2 = 0.0f, s3 = 0.0f;

    // Main 4x-unrolled loop: 8 independent 16B loads issued before any math.
    int i = tid;
    const int stride4 = stride * 4;
    for (; i + 3 * stride < n4; i += stride4) {
        float4 a0 = preds4[i];
        float4 a1 = preds4[i + stride];
        float4 a2 = preds4[i + 2 * stride];
        float4 a3 = preds4[i + 3 * stride];
        float4 b0 = targs4[i];
        float4 b1 = targs4[i + stride];
        float4 b2 = targs4[i + 2 * stride];
        float4 b3 = targs4[i + 3 * stride];

        float t;
        s0 += pair_dist2(a0, b0, t); s0 += t;
        s1 += pair_dist2(a1, b1, t); s1 += t;
        s2 += pair_dist2(a2, b2, t); s2 += t;
        s3 += pair_dist2(a3, b3, t); s3 += t;
    }
    // Remainder float4s
    for (; i < n4; i += stride) {
        float t;
        s0 += pair_dist2(preds4[i], targs4[i], t);
        s0 += t;
    }

    // Tail: odd point count leaves one trailing float2.
    if ((n_points & 1) && blockIdx.x == 0 && threadIdx.x == 0) {
        const float2* p2 = (const float2*)preds4;
        const float2* t2 = (const float2*)targs4;
        float2 a = p2[n_points - 1];
        float2 b = t2[n_points - 1];
        float dx = a.x - b.x, dy = a.y - b.y;
        s0 += sqrtf(fmaf(dx, dx, dy * dy));
    }

    float sum = (s0 + s1) + (s2 + s3);

    // Warp reduce
    #pragma unroll
    for (int off = 16; off > 0; off >>= 1)
        sum += __shfl_down_sync(0xffffffffu, sum, off);

    __shared__ float wsum[RED_THREADS / 32];
    if ((threadIdx.x & 31) == 0)
        wsum[threadIdx.x >> 5] = sum;
    __syncthreads();

    if (threadIdx.x < 32) {
        float v = (threadIdx.x < RED_THREADS / 32) ? wsum[threadIdx.x] : 0.0f;
        #pragma unroll
        for (int off = 4; off > 0; off >>= 1)
            v += __shfl_down_sync(0xffffffffu, v, off);
        if (threadIdx.x == 0)
            g_partials[blockIdx.x] = v;
    }
}

__global__ __launch_bounds__(256)
void dist_reduce_stage2(float* __restrict__ out, double inv_np1)
{
    double s = 0.0;
    for (int i = threadIdx.x; i < RED_BLOCKS; i += blockDim.x)
        s += (double)g_partials[i];

    #pragma unroll
    for (int off = 16; off > 0; off >>= 1)
        s += __shfl_down_sync(0xffffffffu, s, off);

    __shared__ double wsum[8];
    if ((threadIdx.x & 31) == 0)
        wsum[threadIdx.x >> 5] = s;
    __syncthreads();

    if (threadIdx.x == 0) {
        double total = 0.0;
        #pragma unroll
        for (int w = 0; w < 8; w++)
            total += wsum[w];
        out[0] = (float)(total * inv_np1);
    }
}

extern "C" void kernel_launch(void* const* d_in, const int* in_sizes, int n_in,
                              void* d_out, int out_size)
{
    const float4* preds4 = (const float4*)d_in[0];
    const float4* targs4 = (const float4*)d_in[1];
    float* out = (float*)d_out;

    const int total_f = in_sizes[0];     // 2 * N
    const int n_points = total_f / 2;    // N
    const int n4 = total_f / 4;          // float4 count (2 points each)

    dist_reduce_stage1<<<RED_BLOCKS, RED_THREADS>>>(preds4, targs4, n4, n_points);
    dist_reduce_stage2<<<1, 256>>>(out, 1.0 / (double)(n_points + 1));
}

// round 4
// speedup vs baseline: 1.0070x; 1.0070x over previous
#include <cuda_runtime.h>
#include <cuda_bf16.h>

// DIST_loss: loss = sum_i ||preds_i - targets_i||_2 / (N+1)
// preds, targets: [N, 2] float32 (interleaved x,y). Output: 1 float.
//
// Single-kernel HBM-bound streaming reduction with last-block-done finish.
//   - grid-stride, 4x-unrolled float4 streaming loads (__ldcs, 8 independent
//     LDG.128 per iter), 4 independent accumulators
//   - warp+smem block reduce -> g_partials[block]
//   - integer atomic counter; the LAST block to finish reduces all partials
//     in double in a fixed order and writes out * 1/(N+1), then resets the
//     counter so graph replays are self-consistent.
// Deterministic (no float atomics; fixed reduction order), allocation-free,
// graph-capturable (one launch).

#define RED_BLOCKS 2048
#define RED_THREADS 256

__device__ float g_partials[RED_BLOCKS];
__device__ unsigned int g_count = 0;

__device__ __forceinline__ float pair_dist2(float4 a, float4 b, float& s2)
{
    float dx0 = a.x - b.x;
    float dy0 = a.y - b.y;
    float dx1 = a.z - b.z;
    float dy1 = a.w - b.w;
    s2 = sqrtf(fmaf(dx1, dx1, dy1 * dy1));
    return sqrtf(fmaf(dx0, dx0, dy0 * dy0));
}

__global__ __launch_bounds__(RED_THREADS)
void dist_loss_kernel(const float4* __restrict__ preds4,
                      const float4* __restrict__ targs4,
                      int n4, int n_points,
                      float* __restrict__ out, double inv_np1)
{
    const int tid = blockIdx.x * blockDim.x + threadIdx.x;
    const int stride = gridDim.x * blockDim.x;

    float s0 = 0.0f, s1 = 0.0f, s2 = 0.0f, s3 = 0.0f;

    int i = tid;
    const int stride4 = stride * 4;
    for (; i + 3 * stride < n4; i += stride4) {
        float4 a0 = __ldcs(&preds4[i]);
        float4 a1 = __ldcs(&preds4[i + stride]);
        float4 a2 = __ldcs(&preds4[i + 2 * stride]);
        float4 a3 = __ldcs(&preds4[i + 3 * stride]);
        float4 b0 = __ldcs(&targs4[i]);
        float4 b1 = __ldcs(&targs4[i + stride]);
        float4 b2 = __ldcs(&targs4[i + 2 * stride]);
        float4 b3 = __ldcs(&targs4[i + 3 * stride]);

        float t;
        s0 += pair_dist2(a0, b0, t); s0 += t;
        s1 += pair_dist2(a1, b1, t); s1 += t;
        s2 += pair_dist2(a2, b2, t); s2 += t;
        s3 += pair_dist2(a3, b3, t); s3 += t;
    }
    for (; i < n4; i += stride) {
        float t;
        s0 += pair_dist2(__ldcs(&preds4[i]), __ldcs(&targs4[i]), t);
        s0 += t;
    }

    // Tail: odd point count leaves one trailing float2.
    if ((n_points & 1) && blockIdx.x == 0 && threadIdx.x == 0) {
        const float2* p2 = (const float2*)preds4;
        const float2* t2 = (const float2*)targs4;
        float2 a = p2[n_points - 1];
        float2 b = t2[n_points - 1];
        float dx = a.x - b.x, dy = a.y - b.y;
        s0 += sqrtf(fmaf(dx, dx, dy * dy));
    }

    float sum = (s0 + s1) + (s2 + s3);

    // Block reduce
    #pragma unroll
    for (int off = 16; off > 0; off >>= 1)
        sum += __shfl_down_sync(0xffffffffu, sum, off);

    __shared__ float wsum[RED_THREADS / 32];
    if ((threadIdx.x & 31) == 0)
        wsum[threadIdx.x >> 5] = sum;
    __syncthreads();

    __shared__ bool is_last;
    if (threadIdx.x < 32) {
        float v = (threadIdx.x < RED_THREADS / 32) ? wsum[threadIdx.x] : 0.0f;
        #pragma unroll
        for (int off = 4; off > 0; off >>= 1)
            v += __shfl_down_sync(0xffffffffu, v, off);
        if (threadIdx.x == 0) {
            g_partials[blockIdx.x] = v;
            __threadfence();
            unsigned int prev = atomicAdd(&g_count, 1u);
            is_last = (prev == gridDim.x - 1);
        }
    }
    __syncthreads();

    // Last block: deterministic final reduction in double.
    if (is_last) {
        double s = 0.0;
        for (int k = threadIdx.x; k < RED_BLOCKS; k += RED_THREADS)
            s += (double)g_partials[k];

        #pragma unroll
        for (int off = 16; off > 0; off >>= 1)
            s += __shfl_down_sync(0xffffffffu, s, off);

        __shared__ double dsum[RED_THREADS / 32];
        if ((threadIdx.x & 31) == 0)
            dsum[threadIdx.x >> 5] = s;
        __syncthreads();

        if (threadIdx.x == 0) {
            double total = 0.0;
            #pragma unroll
            for (int w = 0; w < RED_THREADS / 32; w++)
                total += dsum[w];
            out[0] = (float)(total * inv_np1);
            g_count = 0;  // reset for next graph replay
        }
    }
}

extern "C" void kernel_launch(void* const* d_in, const int* in_sizes, int n_in,
                              void* d_out, int out_size)
{
    const float4* preds4 = (const float4*)d_in[0];
    const float4* targs4 = (const float4*)d_in[1];
    float* out = (float*)d_out;

    const int total_f = in_sizes[0];     // 2 * N
    const int n_points = total_f / 2;    // N
    const int n4 = total_f / 4;          // float4 count (2 points each)

    dist_loss_kernel<<<RED_BLOCKS, RED_THREADS>>>(
        preds4, targs4, n4, n_points, out, 1.0 / (double)(n_points + 1));
}